// round 14
// baseline (speedup 1.0000x reference)
#include <cuda_runtime.h>
#include <cuda_fp16.h>
#include <math.h>
#include <stdint.h>

// ---------------- problem constants ----------------
#define NB   64
#define NL   1024
#define NT   65536        // NB*NL tokens
#define DM   1024
#define DS   256
#define NIN  28
#define NCL  10
#define NTAP 6
#define KTOT (NTAP*NIN)   // 168
#define KPAD 192          // 6 chunks of 32
#define NCHUNK 6
#define LOGITS_OFF 640    // NB*NCL floats, activations follow

// ---------------- device scratch ----------------
__device__ float g_G [DS*DS];
__device__ float g_G2[DS*DS];
__device__ float g_G4[DS*DS];
__device__ float g_R [NTAP*NIN*DS];      // 168 x 256
__device__ float g_CT[DS*DM];
__device__ float g_bw[NTAP*DS];
__device__ float g_qb[NTAP*DM];
__device__ float g_pooled[NB*DM];
__device__ __half g_Xf[(size_t)NT*KPAD];   // 24MB
__device__ __half g_Qf[(size_t)DM*KPAD];   // [n][k]
__device__ __half g_Yh[(size_t)NT*DM];     // raw Y, half (128MB)

// ---------------- asm helpers ----------------
__device__ __forceinline__ uint32_t smem_u32(const void* p) {
    uint32_t a;
    asm("{ .reg .u64 t; cvta.to.shared.u64 t, %1; cvt.u32.u64 %0, t; }" : "=r"(a) : "l"(p));
    return a;
}
__device__ __forceinline__ void cp16(uint32_t dst, const void* src) {
    asm volatile("cp.async.cg.shared.global [%0], [%1], 16;" :: "r"(dst), "l"(src));
}
__device__ __forceinline__ void cp_commit() {
    asm volatile("cp.async.commit_group;" ::: "memory");
}
__device__ __forceinline__ void cp_wait1() {
    asm volatile("cp.async.wait_group 1;" ::: "memory");
}
__device__ __forceinline__ void cp_wait0() {
    asm volatile("cp.async.wait_group 0;" ::: "memory");
}
__device__ __forceinline__ void ldm_x4(uint32_t* r, uint32_t addr) {
    asm volatile("ldmatrix.sync.aligned.m8n8.x4.shared.b16 {%0,%1,%2,%3}, [%4];"
                 : "=r"(r[0]), "=r"(r[1]), "=r"(r[2]), "=r"(r[3]) : "r"(addr));
}
__device__ __forceinline__ void mma16816(float* c, const uint32_t* a, uint32_t b0, uint32_t b1) {
    asm volatile("mma.sync.aligned.m16n8k16.row.col.f32.f16.f16.f32 "
                 "{%0,%1,%2,%3}, {%4,%5,%6,%7}, {%8,%9}, {%0,%1,%2,%3};"
                 : "+f"(c[0]), "+f"(c[1]), "+f"(c[2]), "+f"(c[3])
                 : "r"(a[0]), "r"(a[1]), "r"(a[2]), "r"(a[3]), "r"(b0), "r"(b1));
}

// ---------------- generic 32x32 fp32 tile (device body) ----------------
__device__ __forceinline__ void tile32(const float* __restrict__ Aa,
                                       const float* __restrict__ Bb,
                                       int M, int N, int K, int m0, int n0,
                                       float acc[2][2],
                                       float As[32][33], float Bs[32][33]) {
    int tx = threadIdx.x & 15, ty = threadIdx.x >> 4;
    acc[0][0] = acc[0][1] = acc[1][0] = acc[1][1] = 0.f;
    for (int k0 = 0; k0 < K; k0 += 32) {
#pragma unroll
        for (int j = 0; j < 4; j++) {
            int e = j*256 + threadIdx.x;
            int r = e >> 5, c = e & 31;
            As[r][c] = (m0+r < M && k0+c < K) ? Aa[(size_t)(m0+r)*K + k0+c] : 0.f;
            Bs[r][c] = (k0+r < K && n0+c < N) ? Bb[(size_t)(k0+r)*N + n0+c] : 0.f;
        }
        __syncthreads();
#pragma unroll
        for (int kk = 0; kk < 32; kk++) {
            float x0 = As[ty*2][kk],  x1 = As[ty*2+1][kk];
            float y0 = Bs[kk][tx*2],  y1 = Bs[kk][tx*2+1];
            acc[0][0] += x0*y0; acc[0][1] += x0*y1;
            acc[1][0] += x1*y0; acc[1][1] += x1*y1;
        }
        __syncthreads();
    }
}

// ---------------- fused small prep: transposes + zero (+ Qf tail zero) --------
__global__ void kt_prep(const float* __restrict__ A, const float* __restrict__ C) {
    int b = blockIdx.x;
    int tid = threadIdx.x;
    if (b < 256) {
        int idx = b*256 + tid;
        int r = idx >> 8, c = idx & 255;
        g_G[c*DS + r] = A[idx];
    } else if (b < 1280) {
        int idx = (b - 256)*256 + tid;
        int r = idx >> 8, c = idx & 255;
        g_CT[c*DM + r] = C[idx];
    } else if (b < 1536) {
        int i = (b - 1280)*256 + tid;
        g_pooled[i] = 0.0f;
    } else {
        int i = (b - 1536)*256 + tid;      // zero all of Qf (covers pad rows)
        ((uint32_t*)g_Qf)[i] = 0u;
    }
}

// bv (coalesced warp gemv) + bw chain, single block
__global__ void kt_bvbias(const float* __restrict__ Bm, const float* __restrict__ b_in) {
    __shared__ float cur[DS];
    __shared__ float bvs[DS];
    int tid = threadIdx.x, lane = tid & 31, warp = tid >> 5;
    for (int r8 = 0; r8 < 32; r8++) {
        int row = warp*32 + r8;
        float s = 0.f;
        for (int k = lane; k < DM; k += 32) s += Bm[(size_t)row*DM + k] * b_in[k];
#pragma unroll
        for (int off = 16; off > 0; off >>= 1) s += __shfl_xor_sync(0xffffffffu, s, off);
        if (lane == 0) bvs[row] = s;
    }
    __syncthreads();
    int c = tid;
    float v = bvs[c];
    cur[c] = v;
    float accum = v;
    g_bw[c] = v;
    for (int s = 1; s < NTAP; s++) {
        __syncthreads();
        float nxt = 0.f;
#pragma unroll 8
        for (int k = 0; k < DS; k++) nxt += cur[k] * g_G[k*DS + c];
        __syncthreads();
        cur[c] = nxt;
        accum += nxt;
        g_bw[s*DS + c] = accum;
    }
}

// L1: blocks 0..63: G2 = G@G ; blocks 64..71: R0 = (Bm@W_in)^T
__global__ void kt_precomp1(const float* __restrict__ Bm, const float* __restrict__ W_in) {
    __shared__ float As[32][33], Bs[32][33];
    float acc[2][2];
    int b = blockIdx.x;
    int tx = threadIdx.x & 15, ty = threadIdx.x >> 4;
    if (b < 64) {
        int m0 = (b >> 3)*32, n0 = (b & 7)*32;
        tile32(g_G, g_G, DS, DS, DS, m0, n0, acc, As, Bs);
        int m = m0 + ty*2, n = n0 + tx*2;
        g_G2[m*DS + n]       = acc[0][0];
        g_G2[m*DS + n+1]     = acc[0][1];
        g_G2[(m+1)*DS + n]   = acc[1][0];
        g_G2[(m+1)*DS + n+1] = acc[1][1];
    } else {
        int m0 = (b - 64)*32;
        tile32(Bm, W_in, DS, NIN, DM, m0, 0, acc, As, Bs);
        int m = m0 + ty*2, n = tx*2;
        if (n   < NIN) { g_R[n*DS + m]     = acc[0][0]; g_R[n*DS + m+1]     = acc[1][0]; }
        if (n+1 < NIN) { g_R[(n+1)*DS + m] = acc[0][1]; g_R[(n+1)*DS + m+1] = acc[1][1]; }
    }
}

// helper: store a 32x32 tile into an R-slab (NIN rows)
__device__ __forceinline__ void storeR(float* Oo, int n0, float acc[2][2]) {
    int tx = threadIdx.x & 15, ty = threadIdx.x >> 4;
    int m = ty*2, n = n0 + tx*2;
    if (m < NIN)   { Oo[m*DS + n] = acc[0][0];     Oo[m*DS + n+1] = acc[0][1]; }
    if (m+1 < NIN) { Oo[(m+1)*DS + n] = acc[1][0]; Oo[(m+1)*DS + n+1] = acc[1][1]; }
}

// L2: blocks 0..63: G4 = G2@G2 ; 64..71: R1 = R0@G ; 72..79: R2 = R0@G2
__global__ void kt_precomp2() {
    __shared__ float As[32][33], Bs[32][33];
    float acc[2][2];
    int b = blockIdx.x;
    if (b < 64) {
        int m0 = (b >> 3)*32, n0 = (b & 7)*32;
        tile32(g_G2, g_G2, DS, DS, DS, m0, n0, acc, As, Bs);
        int tx = threadIdx.x & 15, ty = threadIdx.x >> 4;
        int m = m0 + ty*2, n = n0 + tx*2;
        g_G4[m*DS + n]       = acc[0][0];
        g_G4[m*DS + n+1]     = acc[0][1];
        g_G4[(m+1)*DS + n]   = acc[1][0];
        g_G4[(m+1)*DS + n+1] = acc[1][1];
    } else if (b < 72) {
        int n0 = (b - 64)*32;
        tile32(g_R, g_G, NIN, DS, DS, 0, n0, acc, As, Bs);
        storeR(g_R + 1*NIN*DS, n0, acc);
    } else {
        int n0 = (b - 72)*32;
        tile32(g_R, g_G2, NIN, DS, DS, 0, n0, acc, As, Bs);
        storeR(g_R + 2*NIN*DS, n0, acc);
    }
}

// L3: 0..7: R3 = R1@G2 ; 8..15: R4 = R0@G4 ; 16..23: R5 = R1@G4
__global__ void kt_precomp3() {
    __shared__ float As[32][33], Bs[32][33];
    float acc[2][2];
    int b = blockIdx.x;
    int p = b >> 3, sub = b & 7;
    int n0 = sub*32;
    const float* Aa = (p == 1) ? g_R : g_R + 1*NIN*DS;   // p0:R1, p1:R0, p2:R1
    if (p == 0) {
        tile32(g_R + 1*NIN*DS, g_G2, NIN, DS, DS, 0, n0, acc, As, Bs);
        storeR(g_R + 3*NIN*DS, n0, acc);
    } else if (p == 1) {
        tile32(g_R, g_G4, NIN, DS, DS, 0, n0, acc, As, Bs);
        storeR(g_R + 4*NIN*DS, n0, acc);
    } else {
        tile32(g_R + 1*NIN*DS, g_G4, NIN, DS, DS, 0, n0, acc, As, Bs);
        storeR(g_R + 5*NIN*DS, n0, acc);
    }
    (void)Aa;
}

// L4: [R(168); bw(6)] @ CT -> g_Qf (half, [n][k]) + g_qb (float). 6 x 32 blocks.
__global__ void kt_gemmQ() {
    __shared__ float As[32][33], Bs[32][33];
    int tid = threadIdx.x;
    int tx = tid & 15, ty = tid >> 4;
    int m0 = (int)(blockIdx.x >> 5) * 32;      // 6 m-tiles (174 rows used)
    int n0 = (int)(blockIdx.x & 31) * 32;
    float acc[2][2] = {};
    for (int k0 = 0; k0 < DS; k0 += 32) {
#pragma unroll
        for (int j = 0; j < 4; j++) {
            int e = j*256 + tid;
            int r = e >> 5, c = e & 31;
            int gm = m0 + r;
            float av = 0.f;
            if (gm < KTOT) av = g_R[(size_t)gm*DS + k0 + c];
            else if (gm < KTOT + NTAP) av = g_bw[(gm - KTOT)*DS + k0 + c];
            As[r][c] = av;
            Bs[r][c] = g_CT[(size_t)(k0 + r)*DM + n0 + c];
        }
        __syncthreads();
#pragma unroll
        for (int kk = 0; kk < 32; kk++) {
            float x0 = As[ty*2][kk],  x1 = As[ty*2+1][kk];
            float y0 = Bs[kk][tx*2],  y1 = Bs[kk][tx*2+1];
            acc[0][0] += x0*y0; acc[0][1] += x0*y1;
            acc[1][0] += x1*y0; acc[1][1] += x1*y1;
        }
        __syncthreads();
    }
    int n = n0 + tx*2;
#pragma unroll
    for (int rr = 0; rr < 2; rr++) {
        int m = m0 + ty*2 + rr;
        if (m < KTOT) {
            g_Qf[(size_t)n*KPAD + m]     = __float2half_rn(acc[rr][0]);
            g_Qf[(size_t)(n+1)*KPAD + m] = __float2half_rn(acc[rr][1]);
        } else if (m < KTOT + NTAP) {
            g_qb[(m - KTOT)*DM + n]   = acc[rr][0];
            g_qb[(m - KTOT)*DM + n+1] = acc[rr][1];
        }
    }
}

// ---------------- fp16 X expansion (smem gather, coalesced half2) ----------------
#define XT 64
__global__ void kt_halfX(const float* __restrict__ x) {
    __shared__ float xs[(XT+7)*NIN];
    int tid = threadIdx.x;
    int t0 = blockIdx.x * XT;
    int bbase = t0 & ~(NL-1);
    for (int e = tid; e < (XT+7)*NIN; e += 256) {
        int row = e / NIN, col = e - row*NIN;
        int gt = t0 - 7 + row;
        xs[e] = (gt >= bbase) ? x[(size_t)gt*NIN + col] : 0.f;
    }
    __syncthreads();
    for (int p = tid; p < XT*(KPAD/2); p += 256) {
        int tr = p / (KPAD/2), kp = (p - tr*(KPAD/2))*2;
        float v0 = 0.f, v1 = 0.f;
        if (kp < KTOT) {
            int b0 = kp / NIN, i0 = kp - b0*NIN;
            v0 = xs[(tr + 7 - b0)*NIN + i0];
        }
        if (kp + 1 < KTOT) {
            int b1 = (kp+1) / NIN, i1 = kp+1 - b1*NIN;
            v1 = xs[(tr + 7 - b1)*NIN + i1];
        }
        *(__half2*)&g_Xf[(size_t)(t0+tr)*KPAD + kp] = __floats2half2_rn(v0, v1);
    }
}

// ================= single-pass fp16 mma.sync GEMM: Yh = Xtilde @ Q ============
#define ROWB 80
#define STGB (128*ROWB)
#define EROW 136
__global__ __launch_bounds__(256, 2) void kt_mma() {
    __shared__ __align__(16) char smem[4*STGB];   // 40KB
    char* sA = smem;
    char* sB = smem + 2*STGB;
    const int tid = threadIdx.x, lane = tid & 31, warp = tid >> 5;
    const int wm = warp >> 1, wn = warp & 1;
    const int t0 = (int)(blockIdx.x >> 3) * 128;
    const int n0 = (int)(blockIdx.x & 7) * 128;
    const uint32_t aBase = smem_u32(sA);
    const uint32_t bBase = smem_u32(sB);

    auto issue = [&](int c, int buf) {
        int kb = c * 32;
#pragma unroll
        for (int i = 0; i < 2; i++) {
            int e = i*256 + tid;
            int row = e >> 2, g = e & 3;
            cp16(aBase + buf*STGB + row*ROWB + g*16,
                 g_Xf + (size_t)(t0 + row)*KPAD + kb + g*8);
            cp16(bBase + buf*STGB + row*ROWB + g*16,
                 g_Qf + (size_t)(n0 + row)*KPAD + kb + g*8);
        }
        cp_commit();
    };

    float acc[2][8][4];
#pragma unroll
    for (int mt = 0; mt < 2; mt++)
#pragma unroll
        for (int nt = 0; nt < 8; nt++)
#pragma unroll
            for (int j = 0; j < 4; j++) acc[mt][nt][j] = 0.f;

    issue(0, 0);
    for (int c = 0; c < NCHUNK; c++) {
        int buf = c & 1;
        if (c + 1 < NCHUNK) { issue(c + 1, (c + 1) & 1); cp_wait1(); }
        else cp_wait0();
        __syncthreads();

#pragma unroll
        for (int k16 = 0; k16 < 32; k16 += 16) {
            uint32_t afr[2][4];
#pragma unroll
            for (int mt = 0; mt < 2; mt++) {
                int row = wm*32 + mt*16 + (lane & 15);
                int kk = k16 + ((lane >> 4) << 3);
                ldm_x4(afr[mt], aBase + buf*STGB + row*ROWB + kk*2);
            }
            uint32_t bfr[4][4];
#pragma unroll
            for (int bt = 0; bt < 4; bt++) {
                int n = wn*64 + bt*16 + (lane & 7) + ((lane >> 4) << 3);
                int kk = k16 + (((lane >> 3) & 1) << 3);
                ldm_x4(bfr[bt], bBase + buf*STGB + n*ROWB + kk*2);
            }
#pragma unroll
            for (int mt = 0; mt < 2; mt++)
#pragma unroll
                for (int nt = 0; nt < 8; nt++) {
                    const uint32_t* bp = bfr[nt >> 1];
                    int o = (nt & 1) * 2;
                    mma16816(acc[mt][nt], afr[mt], bp[o], bp[o+1]);
                }
        }
        __syncthreads();
    }

    // epilogue: stage fp32 in smem, store coalesced half4 (uint2) to g_Yh
    float* Ysh = (float*)smem;
    const int qr = lane >> 2, qc = (lane & 3) * 2;
#pragma unroll
    for (int h = 0; h < 2; h++) {
        __syncthreads();
        if ((wm >> 1) == h) {
            int rbase = (wm & 1) * 32;
#pragma unroll
            for (int mt = 0; mt < 2; mt++)
#pragma unroll
                for (int nt = 0; nt < 8; nt++) {
                    int row = rbase + mt*16 + qr;
                    int col = wn*64 + nt*8 + qc;
                    *(float2*)&Ysh[row*EROW + col]     = make_float2(acc[mt][nt][0], acc[mt][nt][1]);
                    *(float2*)&Ysh[(row+8)*EROW + col] = make_float2(acc[mt][nt][2], acc[mt][nt][3]);
                }
        }
        __syncthreads();
#pragma unroll
        for (int i = 0; i < 8; i++) {
            int e = i*256 + tid;
            int row = e >> 5, c4 = e & 31;
            float4 v = *(const float4*)&Ysh[row*EROW + c4*4];
            __half2 h0 = __floats2half2_rn(v.x, v.y);
            __half2 h1 = __floats2half2_rn(v.z, v.w);
            uint2 pk;
            pk.x = *(uint32_t*)&h0;
            pk.y = *(uint32_t*)&h1;
            *(uint2*)&g_Yh[(size_t)(t0 + h*64 + row)*DM + n0 + c4*4] = pk;
        }
    }
}

// ---------------- activation epilogue ----------------
__device__ __forceinline__ float gelu_fast(float y) {
    float z = y * 0.70710678118654752f;
    float z2 = z*z;
    if (z2 < 0.25f) {
        float p = fmaf(z2, 1.0f/216.0f, -1.0f/42.0f);
        p = fmaf(z2, p, 0.1f);
        p = fmaf(z2, p, -1.0f/3.0f);
        p = fmaf(z2, p, 1.0f);
        float e = 1.12837916709551257f * z * p;
        return 0.5f * y * (1.0f + e);
    }
    return 0.5f * y * (1.0f + erff(z));
}
__device__ __forceinline__ float fixv(float v) {
    if (isnan(v)) return 0.f;
    if (isinf(v)) return v > 0.f ? 1000000.0f : -1000000.0f;
    return v;
}

// LN pass: warp-per-16-rows. reads half Y, writes fp32 out. qbias+GELU+LN+pool.
__global__ __launch_bounds__(256) void kt_ln(const float* __restrict__ gamma,
                                             const float* __restrict__ beta,
                                             float* __restrict__ out) {
    const int tid = threadIdx.x, lane = tid & 31, wid = tid >> 5;
    const int wg = blockIdx.x * 8 + wid;
    const int t0 = wg * 16;
    float pool[8][4];
#pragma unroll
    for (int j = 0; j < 8; j++)
#pragma unroll
        for (int q = 0; q < 4; q++) pool[j][q] = 0.f;

    for (int r = 0; r < 16; r++) {
        int t = t0 + r;
        int l = t & (NL-1);
        int s = l < NTAP-1 ? l : NTAP-1;
        float4 v[8];
        float s1 = 0.f, s2 = 0.f;
#pragma unroll
        for (int j = 0; j < 8; j++) {
            uint2 pk = *(const uint2*)&g_Yh[(size_t)t*DM + j*128 + lane*4];
            float2 y0 = __half22float2(*(__half2*)&pk.x);
            float2 y1 = __half22float2(*(__half2*)&pk.y);
            float4 q = *(const float4*)&g_qb[s*DM + j*128 + lane*4];
            v[j].x = gelu_fast(y0.x + q.x);
            v[j].y = gelu_fast(y0.y + q.y);
            v[j].z = gelu_fast(y1.x + q.z);
            v[j].w = gelu_fast(y1.y + q.w);
            s1 += v[j].x + v[j].y + v[j].z + v[j].w;
            s2 += v[j].x*v[j].x + v[j].y*v[j].y + v[j].z*v[j].z + v[j].w*v[j].w;
        }
#pragma unroll
        for (int off = 16; off > 0; off >>= 1) {
            s1 += __shfl_xor_sync(0xffffffffu, s1, off);
            s2 += __shfl_xor_sync(0xffffffffu, s2, off);
        }
        float mu = s1 * (1.0f/DM);
        float rs = rsqrtf(s2 * (1.0f/DM) - mu*mu + 1e-5f);
        size_t o = (size_t)LOGITS_OFF + (size_t)t*DM + lane*4;
#pragma unroll
        for (int j = 0; j < 8; j++) {
            float4 g = *(const float4*)&gamma[j*128 + lane*4];
            float4 b = *(const float4*)&beta[j*128 + lane*4];
            float4 nv;
            nv.x = fixv((v[j].x - mu)*rs*g.x + b.x);
            nv.y = fixv((v[j].y - mu)*rs*g.y + b.y);
            nv.z = fixv((v[j].z - mu)*rs*g.z + b.z);
            nv.w = fixv((v[j].w - mu)*rs*g.w + b.w);
            *(float4*)&out[o + j*128] = nv;
            pool[j][0] += nv.x; pool[j][1] += nv.y; pool[j][2] += nv.z; pool[j][3] += nv.w;
        }
    }
    const float inv = 1.0f / (float)NL;
    const int b = t0 >> 10;
#pragma unroll
    for (int j = 0; j < 8; j++) {
        float* pp = &g_pooled[b*DM + j*128 + lane*4];
        atomicAdd(pp+0, pool[j][0]*inv);
        atomicAdd(pp+1, pool[j][1]*inv);
        atomicAdd(pp+2, pool[j][2]*inv);
        atomicAdd(pp+3, pool[j][3]*inv);
    }
}

// ---------------- logits ----------------
__global__ void kt_logits(const float* __restrict__ W_fc, const float* __restrict__ b_fc,
                          float* __restrict__ out) {
    int b = blockIdx.x;
    int lane = threadIdx.x;
    for (int c = 0; c < NCL; c++) {
        float s = 0.f;
        for (int d = lane; d < DM; d += 32)
            s += g_pooled[b*DM + d] * W_fc[c*DM + d];
#pragma unroll
        for (int off = 16; off > 0; off >>= 1)
            s += __shfl_down_sync(0xffffffffu, s, off);
        if (lane == 0) out[b*NCL + c] = s + b_fc[c];
    }
}

// ---------------- launch ----------------
extern "C" void kernel_launch(void* const* d_in, const int* in_sizes, int n_in,
                              void* d_out, int out_size) {
    const float* x     = (const float*)d_in[0];
    const float* W_in  = (const float*)d_in[1];
    const float* b_in  = (const float*)d_in[2];
    const float* A     = (const float*)d_in[3];
    const float* Bm    = (const float*)d_in[4];
    const float* C     = (const float*)d_in[5];
    const float* gamma = (const float*)d_in[6];
    const float* beta  = (const float*)d_in[7];
    const float* W_fc  = (const float*)d_in[8];
    const float* b_fc  = (const float*)d_in[9];
    float* out = (float*)d_out;

    kt_prep<<<1536 + DM*KPAD/512, 256>>>(A, C);   // G, CT, zero pooled + Qf
    kt_bvbias<<<1, 256>>>(Bm, b_in);              // bw chain (needs G)
    kt_precomp1<<<72, 256>>>(Bm, W_in);           // G2, R0
    kt_precomp2<<<80, 256>>>();                   // G4, R1, R2
    kt_precomp3<<<24, 256>>>();                   // R3, R4, R5
    kt_gemmQ<<<192, 256>>>();                     // Qf (half, [n][k]) + qb
    kt_halfX<<<NT/XT, 256>>>(x);                  // Xf
    kt_mma<<<(NT/128)*8, 256>>>();
    kt_ln<<<NT/128, 256>>>(gamma, beta, out);
    kt_logits<<<NB, 32>>>(W_fc, b_fc, out);
}

// round 15
// speedup vs baseline: 1.0238x; 1.0238x over previous
#include <cuda_runtime.h>
#include <cuda_fp16.h>
#include <math.h>
#include <stdint.h>

// ---------------- problem constants ----------------
#define NB   64
#define NL   1024
#define NT   65536        // NB*NL tokens
#define DM   1024
#define DS   256
#define NIN  28
#define NCL  10
#define NTAP 6
#define KTOT (NTAP*NIN)   // 168
#define KPAD 192          // 6 chunks of 32
#define NCHUNK 6
#define LOGITS_OFF 640    // NB*NCL floats, activations follow

// ---------------- device scratch ----------------
__device__ float g_G [DS*DS];
__device__ float g_G2[DS*DS];
__device__ float g_G4[DS*DS];
__device__ float g_R [NTAP*NIN*DS];      // 168 x 256
__device__ float g_CT[DS*DM];
__device__ float g_bw[NTAP*DS];
__device__ float g_qb[NTAP*DM];
__device__ float g_pooled[NB*DM];
__device__ __half g_Xf[(size_t)NT*KPAD];   // 24MB
__device__ __half g_Qf[(size_t)DM*KPAD];   // [n][k]
__device__ __half g_Yh[(size_t)NT*DM];     // raw Y, half (128MB)

// ---------------- asm helpers ----------------
__device__ __forceinline__ uint32_t smem_u32(const void* p) {
    uint32_t a;
    asm("{ .reg .u64 t; cvta.to.shared.u64 t, %1; cvt.u32.u64 %0, t; }" : "=r"(a) : "l"(p));
    return a;
}
__device__ __forceinline__ void cp16(uint32_t dst, const void* src) {
    asm volatile("cp.async.cg.shared.global [%0], [%1], 16;" :: "r"(dst), "l"(src));
}
__device__ __forceinline__ void cp_commit() {
    asm volatile("cp.async.commit_group;" ::: "memory");
}
__device__ __forceinline__ void cp_wait1() {
    asm volatile("cp.async.wait_group 1;" ::: "memory");
}
__device__ __forceinline__ void cp_wait0() {
    asm volatile("cp.async.wait_group 0;" ::: "memory");
}
__device__ __forceinline__ void ldm_x4(uint32_t* r, uint32_t addr) {
    asm volatile("ldmatrix.sync.aligned.m8n8.x4.shared.b16 {%0,%1,%2,%3}, [%4];"
                 : "=r"(r[0]), "=r"(r[1]), "=r"(r[2]), "=r"(r[3]) : "r"(addr));
}
__device__ __forceinline__ void mma16816(float* c, const uint32_t* a, uint32_t b0, uint32_t b1) {
    asm volatile("mma.sync.aligned.m16n8k16.row.col.f32.f16.f16.f32 "
                 "{%0,%1,%2,%3}, {%4,%5,%6,%7}, {%8,%9}, {%0,%1,%2,%3};"
                 : "+f"(c[0]), "+f"(c[1]), "+f"(c[2]), "+f"(c[3])
                 : "r"(a[0]), "r"(a[1]), "r"(a[2]), "r"(a[3]), "r"(b0), "r"(b1));
}

// ---------------- generic 32x32 fp32 tile (device body) ----------------
__device__ __forceinline__ void tile32(const float* __restrict__ Aa,
                                       const float* __restrict__ Bb,
                                       int M, int N, int K, int m0, int n0,
                                       float acc[2][2],
                                       float As[32][33], float Bs[32][33]) {
    int tx = threadIdx.x & 15, ty = threadIdx.x >> 4;
    acc[0][0] = acc[0][1] = acc[1][0] = acc[1][1] = 0.f;
    for (int k0 = 0; k0 < K; k0 += 32) {
#pragma unroll
        for (int j = 0; j < 4; j++) {
            int e = j*256 + threadIdx.x;
            int r = e >> 5, c = e & 31;
            As[r][c] = (m0+r < M && k0+c < K) ? Aa[(size_t)(m0+r)*K + k0+c] : 0.f;
            Bs[r][c] = (k0+r < K && n0+c < N) ? Bb[(size_t)(k0+r)*N + n0+c] : 0.f;
        }
        __syncthreads();
#pragma unroll
        for (int kk = 0; kk < 32; kk++) {
            float x0 = As[ty*2][kk],  x1 = As[ty*2+1][kk];
            float y0 = Bs[kk][tx*2],  y1 = Bs[kk][tx*2+1];
            acc[0][0] += x0*y0; acc[0][1] += x0*y1;
            acc[1][0] += x1*y0; acc[1][1] += x1*y1;
        }
        __syncthreads();
    }
}

// ---------------- fused small prep: transposes + zero (+ Qf tail zero) --------
__global__ void kt_prep(const float* __restrict__ A, const float* __restrict__ C) {
    int b = blockIdx.x;
    int tid = threadIdx.x;
    if (b < 256) {
        int idx = b*256 + tid;
        int r = idx >> 8, c = idx & 255;
        g_G[c*DS + r] = A[idx];
    } else if (b < 1280) {
        int idx = (b - 256)*256 + tid;
        int r = idx >> 8, c = idx & 255;
        g_CT[c*DM + r] = C[idx];
    } else if (b < 1536) {
        int i = (b - 1280)*256 + tid;
        g_pooled[i] = 0.0f;
    } else {
        int i = (b - 1536)*256 + tid;      // zero all of Qf (covers pad rows)
        ((uint32_t*)g_Qf)[i] = 0u;
    }
}

// bv (coalesced warp gemv) + bw chain, single block
__global__ void kt_bvbias(const float* __restrict__ Bm, const float* __restrict__ b_in) {
    __shared__ float cur[DS];
    __shared__ float bvs[DS];
    int tid = threadIdx.x, lane = tid & 31, warp = tid >> 5;
    for (int r8 = 0; r8 < 32; r8++) {
        int row = warp*32 + r8;
        float s = 0.f;
        for (int k = lane; k < DM; k += 32) s += Bm[(size_t)row*DM + k] * b_in[k];
#pragma unroll
        for (int off = 16; off > 0; off >>= 1) s += __shfl_xor_sync(0xffffffffu, s, off);
        if (lane == 0) bvs[row] = s;
    }
    __syncthreads();
    int c = tid;
    float v = bvs[c];
    cur[c] = v;
    float accum = v;
    g_bw[c] = v;
    for (int s = 1; s < NTAP; s++) {
        __syncthreads();
        float nxt = 0.f;
#pragma unroll 8
        for (int k = 0; k < DS; k++) nxt += cur[k] * g_G[k*DS + c];
        __syncthreads();
        cur[c] = nxt;
        accum += nxt;
        g_bw[s*DS + c] = accum;
    }
}

// L1: blocks 0..63: G2 = G@G ; blocks 64..71: R0 = (Bm@W_in)^T
__global__ void kt_precomp1(const float* __restrict__ Bm, const float* __restrict__ W_in) {
    __shared__ float As[32][33], Bs[32][33];
    float acc[2][2];
    int b = blockIdx.x;
    int tx = threadIdx.x & 15, ty = threadIdx.x >> 4;
    if (b < 64) {
        int m0 = (b >> 3)*32, n0 = (b & 7)*32;
        tile32(g_G, g_G, DS, DS, DS, m0, n0, acc, As, Bs);
        int m = m0 + ty*2, n = n0 + tx*2;
        g_G2[m*DS + n]       = acc[0][0];
        g_G2[m*DS + n+1]     = acc[0][1];
        g_G2[(m+1)*DS + n]   = acc[1][0];
        g_G2[(m+1)*DS + n+1] = acc[1][1];
    } else {
        int m0 = (b - 64)*32;
        tile32(Bm, W_in, DS, NIN, DM, m0, 0, acc, As, Bs);
        int m = m0 + ty*2, n = tx*2;
        if (n   < NIN) { g_R[n*DS + m]     = acc[0][0]; g_R[n*DS + m+1]     = acc[1][0]; }
        if (n+1 < NIN) { g_R[(n+1)*DS + m] = acc[0][1]; g_R[(n+1)*DS + m+1] = acc[1][1]; }
    }
}

// helper: store a 32x32 tile into an R-slab (NIN rows)
__device__ __forceinline__ void storeR(float* Oo, int n0, float acc[2][2]) {
    int tx = threadIdx.x & 15, ty = threadIdx.x >> 4;
    int m = ty*2, n = n0 + tx*2;
    if (m < NIN)   { Oo[m*DS + n] = acc[0][0];     Oo[m*DS + n+1] = acc[0][1]; }
    if (m+1 < NIN) { Oo[(m+1)*DS + n] = acc[1][0]; Oo[(m+1)*DS + n+1] = acc[1][1]; }
}

// L2: blocks 0..63: G4 = G2@G2 ; 64..71: R1 = R0@G ; 72..79: R2 = R0@G2
__global__ void kt_precomp2() {
    __shared__ float As[32][33], Bs[32][33];
    float acc[2][2];
    int b = blockIdx.x;
    if (b < 64) {
        int m0 = (b >> 3)*32, n0 = (b & 7)*32;
        tile32(g_G2, g_G2, DS, DS, DS, m0, n0, acc, As, Bs);
        int tx = threadIdx.x & 15, ty = threadIdx.x >> 4;
        int m = m0 + ty*2, n = n0 + tx*2;
        g_G4[m*DS + n]       = acc[0][0];
        g_G4[m*DS + n+1]     = acc[0][1];
        g_G4[(m+1)*DS + n]   = acc[1][0];
        g_G4[(m+1)*DS + n+1] = acc[1][1];
    } else if (b < 72) {
        int n0 = (b - 64)*32;
        tile32(g_R, g_G, NIN, DS, DS, 0, n0, acc, As, Bs);
        storeR(g_R + 1*NIN*DS, n0, acc);
    } else {
        int n0 = (b - 72)*32;
        tile32(g_R, g_G2, NIN, DS, DS, 0, n0, acc, As, Bs);
        storeR(g_R + 2*NIN*DS, n0, acc);
    }
}

// L3: 0..7: R3 = R1@G2 ; 8..15: R4 = R0@G4 ; 16..23: R5 = R1@G4
__global__ void kt_precomp3() {
    __shared__ float As[32][33], Bs[32][33];
    float acc[2][2];
    int b = blockIdx.x;
    int p = b >> 3, sub = b & 7;
    int n0 = sub*32;
    const float* Aa = (p == 1) ? g_R : g_R + 1*NIN*DS;   // p0:R1, p1:R0, p2:R1
    if (p == 0) {
        tile32(g_R + 1*NIN*DS, g_G2, NIN, DS, DS, 0, n0, acc, As, Bs);
        storeR(g_R + 3*NIN*DS, n0, acc);
    } else if (p == 1) {
        tile32(g_R, g_G4, NIN, DS, DS, 0, n0, acc, As, Bs);
        storeR(g_R + 4*NIN*DS, n0, acc);
    } else {
        tile32(g_R + 1*NIN*DS, g_G4, NIN, DS, DS, 0, n0, acc, As, Bs);
        storeR(g_R + 5*NIN*DS, n0, acc);
    }
    (void)Aa;
}

// L4: [R(168); bw(6)] @ CT -> g_Qf (half, [n][k]) + g_qb (float). 6 x 32 blocks.
__global__ void kt_gemmQ() {
    __shared__ float As[32][33], Bs[32][33];
    int tid = threadIdx.x;
    int tx = tid & 15, ty = tid >> 4;
    int m0 = (int)(blockIdx.x >> 5) * 32;      // 6 m-tiles (174 rows used)
    int n0 = (int)(blockIdx.x & 31) * 32;
    float acc[2][2] = {};
    for (int k0 = 0; k0 < DS; k0 += 32) {
#pragma unroll
        for (int j = 0; j < 4; j++) {
            int e = j*256 + tid;
            int r = e >> 5, c = e & 31;
            int gm = m0 + r;
            float av = 0.f;
            if (gm < KTOT) av = g_R[(size_t)gm*DS + k0 + c];
            else if (gm < KTOT + NTAP) av = g_bw[(gm - KTOT)*DS + k0 + c];
            As[r][c] = av;
            Bs[r][c] = g_CT[(size_t)(k0 + r)*DM + n0 + c];
        }
        __syncthreads();
#pragma unroll
        for (int kk = 0; kk < 32; kk++) {
            float x0 = As[ty*2][kk],  x1 = As[ty*2+1][kk];
            float y0 = Bs[kk][tx*2],  y1 = Bs[kk][tx*2+1];
            acc[0][0] += x0*y0; acc[0][1] += x0*y1;
            acc[1][0] += x1*y0; acc[1][1] += x1*y1;
        }
        __syncthreads();
    }
    int n = n0 + tx*2;
#pragma unroll
    for (int rr = 0; rr < 2; rr++) {
        int m = m0 + ty*2 + rr;
        if (m < KTOT) {
            g_Qf[(size_t)n*KPAD + m]     = __float2half_rn(acc[rr][0]);
            g_Qf[(size_t)(n+1)*KPAD + m] = __float2half_rn(acc[rr][1]);
        } else if (m < KTOT + NTAP) {
            g_qb[(m - KTOT)*DM + n]   = acc[rr][0];
            g_qb[(m - KTOT)*DM + n+1] = acc[rr][1];
        }
    }
}

// ---------------- fp16 X expansion (smem gather, coalesced half2) ----------------
#define XT 64
__global__ void kt_halfX(const float* __restrict__ x) {
    __shared__ float xs[(XT+7)*NIN];
    int tid = threadIdx.x;
    int t0 = blockIdx.x * XT;
    int bbase = t0 & ~(NL-1);
    for (int e = tid; e < (XT+7)*NIN; e += 256) {
        int row = e / NIN, col = e - row*NIN;
        int gt = t0 - 7 + row;
        xs[e] = (gt >= bbase) ? x[(size_t)gt*NIN + col] : 0.f;
    }
    __syncthreads();
    for (int p = tid; p < XT*(KPAD/2); p += 256) {
        int tr = p / (KPAD/2), kp = (p - tr*(KPAD/2))*2;
        float v0 = 0.f, v1 = 0.f;
        if (kp < KTOT) {
            int b0 = kp / NIN, i0 = kp - b0*NIN;
            v0 = xs[(tr + 7 - b0)*NIN + i0];
        }
        if (kp + 1 < KTOT) {
            int b1 = (kp+1) / NIN, i1 = kp+1 - b1*NIN;
            v1 = xs[(tr + 7 - b1)*NIN + i1];
        }
        *(__half2*)&g_Xf[(size_t)(t0+tr)*KPAD + kp] = __floats2half2_rn(v0, v1);
    }
}

// ================= single-pass fp16 mma.sync GEMM: Yh = Xtilde @ Q ============
#define ROWB 80
#define STGB (128*ROWB)
#define EROW 136
__global__ __launch_bounds__(256, 2) void kt_mma() {
    __shared__ __align__(16) char smem[4*STGB];   // 40KB
    char* sA = smem;
    char* sB = smem + 2*STGB;
    const int tid = threadIdx.x, lane = tid & 31, warp = tid >> 5;
    const int wm = warp >> 1, wn = warp & 1;
    const int t0 = (int)(blockIdx.x >> 3) * 128;
    const int n0 = (int)(blockIdx.x & 7) * 128;
    const uint32_t aBase = smem_u32(sA);
    const uint32_t bBase = smem_u32(sB);

    auto issue = [&](int c, int buf) {
        int kb = c * 32;
#pragma unroll
        for (int i = 0; i < 2; i++) {
            int e = i*256 + tid;
            int row = e >> 2, g = e & 3;
            cp16(aBase + buf*STGB + row*ROWB + g*16,
                 g_Xf + (size_t)(t0 + row)*KPAD + kb + g*8);
            cp16(bBase + buf*STGB + row*ROWB + g*16,
                 g_Qf + (size_t)(n0 + row)*KPAD + kb + g*8);
        }
        cp_commit();
    };

    float acc[2][8][4];
#pragma unroll
    for (int mt = 0; mt < 2; mt++)
#pragma unroll
        for (int nt = 0; nt < 8; nt++)
#pragma unroll
            for (int j = 0; j < 4; j++) acc[mt][nt][j] = 0.f;

    issue(0, 0);
    for (int c = 0; c < NCHUNK; c++) {
        int buf = c & 1;
        if (c + 1 < NCHUNK) { issue(c + 1, (c + 1) & 1); cp_wait1(); }
        else cp_wait0();
        __syncthreads();

#pragma unroll
        for (int k16 = 0; k16 < 32; k16 += 16) {
            uint32_t afr[2][4];
#pragma unroll
            for (int mt = 0; mt < 2; mt++) {
                int row = wm*32 + mt*16 + (lane & 15);
                int kk = k16 + ((lane >> 4) << 3);
                ldm_x4(afr[mt], aBase + buf*STGB + row*ROWB + kk*2);
            }
            uint32_t bfr[4][4];
#pragma unroll
            for (int bt = 0; bt < 4; bt++) {
                int n = wn*64 + bt*16 + (lane & 7) + ((lane >> 4) << 3);
                int kk = k16 + (((lane >> 3) & 1) << 3);
                ldm_x4(bfr[bt], bBase + buf*STGB + n*ROWB + kk*2);
            }
#pragma unroll
            for (int mt = 0; mt < 2; mt++)
#pragma unroll
                for (int nt = 0; nt < 8; nt++) {
                    const uint32_t* bp = bfr[nt >> 1];
                    int o = (nt & 1) * 2;
                    mma16816(acc[mt][nt], afr[mt], bp[o], bp[o+1]);
                }
        }
        __syncthreads();
    }

    // epilogue: stage fp32 in smem, store coalesced half4 (uint2) to g_Yh
    float* Ysh = (float*)smem;
    const int qr = lane >> 2, qc = (lane & 3) * 2;
#pragma unroll
    for (int h = 0; h < 2; h++) {
        __syncthreads();
        if ((wm >> 1) == h) {
            int rbase = (wm & 1) * 32;
#pragma unroll
            for (int mt = 0; mt < 2; mt++)
#pragma unroll
                for (int nt = 0; nt < 8; nt++) {
                    int row = rbase + mt*16 + qr;
                    int col = wn*64 + nt*8 + qc;
                    *(float2*)&Ysh[row*EROW + col]     = make_float2(acc[mt][nt][0], acc[mt][nt][1]);
                    *(float2*)&Ysh[(row+8)*EROW + col] = make_float2(acc[mt][nt][2], acc[mt][nt][3]);
                }
        }
        __syncthreads();
#pragma unroll
        for (int i = 0; i < 8; i++) {
            int e = i*256 + tid;
            int row = e >> 5, c4 = e & 31;
            float4 v = *(const float4*)&Ysh[row*EROW + c4*4];
            __half2 h0 = __floats2half2_rn(v.x, v.y);
            __half2 h1 = __floats2half2_rn(v.z, v.w);
            uint2 pk;
            pk.x = *(uint32_t*)&h0;
            pk.y = *(uint32_t*)&h1;
            *(uint2*)&g_Yh[(size_t)(t0 + h*64 + row)*DM + n0 + c4*4] = pk;
        }
    }
}

// ---------------- activation epilogue ----------------
__device__ __forceinline__ float gelu_fast(float y) {
    float z = y * 0.70710678118654752f;
    float z2 = z*z;
    if (z2 < 0.25f) {
        float p = fmaf(z2, 1.0f/216.0f, -1.0f/42.0f);
        p = fmaf(z2, p, 0.1f);
        p = fmaf(z2, p, -1.0f/3.0f);
        p = fmaf(z2, p, 1.0f);
        float e = 1.12837916709551257f * z * p;
        return 0.5f * y * (1.0f + e);
    }
    return 0.5f * y * (1.0f + erff(z));
}
__device__ __forceinline__ float fixv(float v) {
    if (isnan(v)) return 0.f;
    if (isinf(v)) return v > 0.f ? 1000000.0f : -1000000.0f;
    return v;
}

// LN pass: warp-per-16-rows. reads half Y, writes fp32 out. qbias+GELU+LN+pool.
__global__ __launch_bounds__(256) void kt_ln(const float* __restrict__ gamma,
                                             const float* __restrict__ beta,
                                             float* __restrict__ out) {
    const int tid = threadIdx.x, lane = tid & 31, wid = tid >> 5;
    const int wg = blockIdx.x * 8 + wid;
    const int t0 = wg * 16;
    float pool[8][4];
#pragma unroll
    for (int j = 0; j < 8; j++)
#pragma unroll
        for (int q = 0; q < 4; q++) pool[j][q] = 0.f;

    for (int r = 0; r < 16; r++) {
        int t = t0 + r;
        int l = t & (NL-1);
        int s = l < NTAP-1 ? l : NTAP-1;
        float4 v[8];
        float s1 = 0.f, s2 = 0.f;
#pragma unroll
        for (int j = 0; j < 8; j++) {
            uint2 pk = *(const uint2*)&g_Yh[(size_t)t*DM + j*128 + lane*4];
            float2 y0 = __half22float2(*(__half2*)&pk.x);
            float2 y1 = __half22float2(*(__half2*)&pk.y);
            float4 q = *(const float4*)&g_qb[s*DM + j*128 + lane*4];
            v[j].x = gelu_fast(y0.x + q.x);
            v[j].y = gelu_fast(y0.y + q.y);
            v[j].z = gelu_fast(y1.x + q.z);
            v[j].w = gelu_fast(y1.y + q.w);
            s1 += v[j].x + v[j].y + v[j].z + v[j].w;
            s2 += v[j].x*v[j].x + v[j].y*v[j].y + v[j].z*v[j].z + v[j].w*v[j].w;
        }
#pragma unroll
        for (int off = 16; off > 0; off >>= 1) {
            s1 += __shfl_xor_sync(0xffffffffu, s1, off);
            s2 += __shfl_xor_sync(0xffffffffu, s2, off);
        }
        float mu = s1 * (1.0f/DM);
        float rs = rsqrtf(s2 * (1.0f/DM) - mu*mu + 1e-5f);
        size_t o = (size_t)LOGITS_OFF + (size_t)t*DM + lane*4;
#pragma unroll
        for (int j = 0; j < 8; j++) {
            float4 g = *(const float4*)&gamma[j*128 + lane*4];
            float4 b = *(const float4*)&beta[j*128 + lane*4];
            float4 nv;
            nv.x = fixv((v[j].x - mu)*rs*g.x + b.x);
            nv.y = fixv((v[j].y - mu)*rs*g.y + b.y);
            nv.z = fixv((v[j].z - mu)*rs*g.z + b.z);
            nv.w = fixv((v[j].w - mu)*rs*g.w + b.w);
            *(float4*)&out[o + j*128] = nv;
            pool[j][0] += nv.x; pool[j][1] += nv.y; pool[j][2] += nv.z; pool[j][3] += nv.w;
        }
    }
    const float inv = 1.0f / (float)NL;
    const int b = t0 >> 10;
#pragma unroll
    for (int j = 0; j < 8; j++) {
        float* pp = &g_pooled[b*DM + j*128 + lane*4];
        atomicAdd(pp+0, pool[j][0]*inv);
        atomicAdd(pp+1, pool[j][1]*inv);
        atomicAdd(pp+2, pool[j][2]*inv);
        atomicAdd(pp+3, pool[j][3]*inv);
    }
}

// ---------------- logits ----------------
__global__ void kt_logits(const float* __restrict__ W_fc, const float* __restrict__ b_fc,
                          float* __restrict__ out) {
    int b = blockIdx.x;
    int lane = threadIdx.x;
    for (int c = 0; c < NCL; c++) {
        float s = 0.f;
        for (int d = lane; d < DM; d += 32)
            s += g_pooled[b*DM + d] * W_fc[c*DM + d];
#pragma unroll
        for (int off = 16; off > 0; off >>= 1)
            s += __shfl_down_sync(0xffffffffu, s, off);
        if (lane == 0) out[b*NCL + c] = s + b_fc[c];
    }
}

// ---------------- launch ----------------
extern "C" void kernel_launch(void* const* d_in, const int* in_sizes, int n_in,
                              void* d_out, int out_size) {
    const float* x     = (const float*)d_in[0];
    const float* W_in  = (const float*)d_in[1];
    const float* b_in  = (const float*)d_in[2];
    const float* A     = (const float*)d_in[3];
    const float* Bm    = (const float*)d_in[4];
    const float* C     = (const float*)d_in[5];
    const float* gamma = (const float*)d_in[6];
    const float* beta  = (const float*)d_in[7];
    const float* W_fc  = (const float*)d_in[8];
    const float* b_fc  = (const float*)d_in[9];
    float* out = (float*)d_out;

    kt_prep<<<1536 + DM*KPAD/512, 256>>>(A, C);   // G, CT, zero pooled + Qf
    kt_bvbias<<<1, 256>>>(Bm, b_in);              // bw chain (needs G)
    kt_precomp1<<<72, 256>>>(Bm, W_in);           // G2, R0
    kt_precomp2<<<80, 256>>>();                   // G4, R1, R2
    kt_precomp3<<<24, 256>>>();                   // R3, R4, R5
    kt_gemmQ<<<192, 256>>>();                     // Qf (half, [n][k]) + qb
    kt_halfX<<<NT/XT, 256>>>(x);                  // Xf
    kt_mma<<<(NT/128)*8, 256>>>();
    kt_ln<<<NT/128, 256>>>(gamma, beta, out);
    kt_logits<<<NB, 32>>>(W_fc, b_fc, out);
}

// round 16
// speedup vs baseline: 1.0300x; 1.0061x over previous
#include <cuda_runtime.h>
#include <cuda_fp16.h>
#include <math.h>
#include <stdint.h>

// ---------------- problem constants ----------------
#define NB   64
#define NL   1024
#define NT   65536        // NB*NL tokens
#define DM   1024
#define DS   256
#define NIN  28
#define NCL  10
#define NTAP 6
#define KTOT (NTAP*NIN)   // 168
#define KPAD 192          // 6 chunks of 32
#define NCHUNK 6
#define LOGITS_OFF 640    // NB*NCL floats, activations follow

// ---------------- device scratch ----------------
__device__ float g_G [DS*DS];
__device__ float g_G2[DS*DS];
__device__ float g_G4[DS*DS];
__device__ float g_R [NTAP*NIN*DS];      // 168 x 256
__device__ float g_CT[DS*DM];
__device__ float g_bw[NTAP*DS];
__device__ float g_qb[NTAP*DM];
__device__ float g_pooled[NB*DM];
__device__ __half g_Xf[(size_t)NT*KPAD];   // 24MB
__device__ __half g_Qf[(size_t)DM*KPAD];   // [n][k]

// ---------------- asm helpers ----------------
__device__ __forceinline__ uint32_t smem_u32(const void* p) {
    uint32_t a;
    asm("{ .reg .u64 t; cvta.to.shared.u64 t, %1; cvt.u32.u64 %0, t; }" : "=r"(a) : "l"(p));
    return a;
}
__device__ __forceinline__ void cp16(uint32_t dst, const void* src) {
    asm volatile("cp.async.cg.shared.global [%0], [%1], 16;" :: "r"(dst), "l"(src));
}
__device__ __forceinline__ void cp_commit() {
    asm volatile("cp.async.commit_group;" ::: "memory");
}
__device__ __forceinline__ void cp_wait1() {
    asm volatile("cp.async.wait_group 1;" ::: "memory");
}
__device__ __forceinline__ void cp_wait0() {
    asm volatile("cp.async.wait_group 0;" ::: "memory");
}
__device__ __forceinline__ void ldm_x4(uint32_t* r, uint32_t addr) {
    asm volatile("ldmatrix.sync.aligned.m8n8.x4.shared.b16 {%0,%1,%2,%3}, [%4];"
                 : "=r"(r[0]), "=r"(r[1]), "=r"(r[2]), "=r"(r[3]) : "r"(addr));
}
__device__ __forceinline__ void mma16816(float* c, const uint32_t* a, uint32_t b0, uint32_t b1) {
    asm volatile("mma.sync.aligned.m16n8k16.row.col.f32.f16.f16.f32 "
                 "{%0,%1,%2,%3}, {%4,%5,%6,%7}, {%8,%9}, {%0,%1,%2,%3};"
                 : "+f"(c[0]), "+f"(c[1]), "+f"(c[2]), "+f"(c[3])
                 : "r"(a[0]), "r"(a[1]), "r"(a[2]), "r"(a[3]), "r"(b0), "r"(b1));
}

// ---------------- generic 32x32 fp32 tile (device body) ----------------
__device__ __forceinline__ void tile32(const float* __restrict__ Aa,
                                       const float* __restrict__ Bb,
                                       int M, int N, int K, int m0, int n0,
                                       float acc[2][2],
                                       float As[32][33], float Bs[32][33]) {
    int tx = threadIdx.x & 15, ty = threadIdx.x >> 4;
    acc[0][0] = acc[0][1] = acc[1][0] = acc[1][1] = 0.f;
    for (int k0 = 0; k0 < K; k0 += 32) {
#pragma unroll
        for (int j = 0; j < 4; j++) {
            int e = j*256 + threadIdx.x;
            int r = e >> 5, c = e & 31;
            As[r][c] = (m0+r < M && k0+c < K) ? Aa[(size_t)(m0+r)*K + k0+c] : 0.f;
            Bs[r][c] = (k0+r < K && n0+c < N) ? Bb[(size_t)(k0+r)*N + n0+c] : 0.f;
        }
        __syncthreads();
#pragma unroll
        for (int kk = 0; kk < 32; kk++) {
            float x0 = As[ty*2][kk],  x1 = As[ty*2+1][kk];
            float y0 = Bs[kk][tx*2],  y1 = Bs[kk][tx*2+1];
            acc[0][0] += x0*y0; acc[0][1] += x0*y1;
            acc[1][0] += x1*y0; acc[1][1] += x1*y1;
        }
        __syncthreads();
    }
}

// ---------------- fused small prep: transposes + zero (+ Qf tail zero) --------
__global__ void kt_prep(const float* __restrict__ A, const float* __restrict__ C) {
    int b = blockIdx.x;
    int tid = threadIdx.x;
    if (b < 256) {
        int idx = b*256 + tid;
        int r = idx >> 8, c = idx & 255;
        g_G[c*DS + r] = A[idx];
    } else if (b < 1280) {
        int idx = (b - 256)*256 + tid;
        int r = idx >> 8, c = idx & 255;
        g_CT[c*DM + r] = C[idx];
    } else if (b < 1536) {
        int i = (b - 1280)*256 + tid;
        g_pooled[i] = 0.0f;
    } else {
        int i = (b - 1536)*256 + tid;      // zero all of Qf (covers pad rows)
        ((uint32_t*)g_Qf)[i] = 0u;
    }
}

// bv (coalesced warp gemv) + bw chain, single block
__global__ void kt_bvbias(const float* __restrict__ Bm, const float* __restrict__ b_in) {
    __shared__ float cur[DS];
    __shared__ float bvs[DS];
    int tid = threadIdx.x, lane = tid & 31, warp = tid >> 5;
    for (int r8 = 0; r8 < 32; r8++) {
        int row = warp*32 + r8;
        float s = 0.f;
        for (int k = lane; k < DM; k += 32) s += Bm[(size_t)row*DM + k] * b_in[k];
#pragma unroll
        for (int off = 16; off > 0; off >>= 1) s += __shfl_xor_sync(0xffffffffu, s, off);
        if (lane == 0) bvs[row] = s;
    }
    __syncthreads();
    int c = tid;
    float v = bvs[c];
    cur[c] = v;
    float accum = v;
    g_bw[c] = v;
    for (int s = 1; s < NTAP; s++) {
        __syncthreads();
        float nxt = 0.f;
#pragma unroll 8
        for (int k = 0; k < DS; k++) nxt += cur[k] * g_G[k*DS + c];
        __syncthreads();
        cur[c] = nxt;
        accum += nxt;
        g_bw[s*DS + c] = accum;
    }
}

// L1: blocks 0..63: G2 = G@G ; blocks 64..71: R0 = (Bm@W_in)^T
__global__ void kt_precomp1(const float* __restrict__ Bm, const float* __restrict__ W_in) {
    __shared__ float As[32][33], Bs[32][33];
    float acc[2][2];
    int b = blockIdx.x;
    int tx = threadIdx.x & 15, ty = threadIdx.x >> 4;
    if (b < 64) {
        int m0 = (b >> 3)*32, n0 = (b & 7)*32;
        tile32(g_G, g_G, DS, DS, DS, m0, n0, acc, As, Bs);
        int m = m0 + ty*2, n = n0 + tx*2;
        g_G2[m*DS + n]       = acc[0][0];
        g_G2[m*DS + n+1]     = acc[0][1];
        g_G2[(m+1)*DS + n]   = acc[1][0];
        g_G2[(m+1)*DS + n+1] = acc[1][1];
    } else {
        int m0 = (b - 64)*32;
        tile32(Bm, W_in, DS, NIN, DM, m0, 0, acc, As, Bs);
        int m = m0 + ty*2, n = tx*2;
        if (n   < NIN) { g_R[n*DS + m]     = acc[0][0]; g_R[n*DS + m+1]     = acc[1][0]; }
        if (n+1 < NIN) { g_R[(n+1)*DS + m] = acc[0][1]; g_R[(n+1)*DS + m+1] = acc[1][1]; }
    }
}

// helper: store a 32x32 tile into an R-slab (NIN rows)
__device__ __forceinline__ void storeR(float* Oo, int n0, float acc[2][2]) {
    int tx = threadIdx.x & 15, ty = threadIdx.x >> 4;
    int m = ty*2, n = n0 + tx*2;
    if (m < NIN)   { Oo[m*DS + n] = acc[0][0];     Oo[m*DS + n+1] = acc[0][1]; }
    if (m+1 < NIN) { Oo[(m+1)*DS + n] = acc[1][0]; Oo[(m+1)*DS + n+1] = acc[1][1]; }
}

// L2: blocks 0..63: G4 = G2@G2 ; 64..71: R1 = R0@G ; 72..79: R2 = R0@G2
__global__ void kt_precomp2() {
    __shared__ float As[32][33], Bs[32][33];
    float acc[2][2];
    int b = blockIdx.x;
    if (b < 64) {
        int m0 = (b >> 3)*32, n0 = (b & 7)*32;
        tile32(g_G2, g_G2, DS, DS, DS, m0, n0, acc, As, Bs);
        int tx = threadIdx.x & 15, ty = threadIdx.x >> 4;
        int m = m0 + ty*2, n = n0 + tx*2;
        g_G4[m*DS + n]       = acc[0][0];
        g_G4[m*DS + n+1]     = acc[0][1];
        g_G4[(m+1)*DS + n]   = acc[1][0];
        g_G4[(m+1)*DS + n+1] = acc[1][1];
    } else if (b < 72) {
        int n0 = (b - 64)*32;
        tile32(g_R, g_G, NIN, DS, DS, 0, n0, acc, As, Bs);
        storeR(g_R + 1*NIN*DS, n0, acc);
    } else {
        int n0 = (b - 72)*32;
        tile32(g_R, g_G2, NIN, DS, DS, 0, n0, acc, As, Bs);
        storeR(g_R + 2*NIN*DS, n0, acc);
    }
}

// L3: 0..7: R3 = R1@G2 ; 8..15: R4 = R0@G4 ; 16..23: R5 = R1@G4
__global__ void kt_precomp3() {
    __shared__ float As[32][33], Bs[32][33];
    float acc[2][2];
    int b = blockIdx.x;
    int p = b >> 3, sub = b & 7;
    int n0 = sub*32;
    if (p == 0) {
        tile32(g_R + 1*NIN*DS, g_G2, NIN, DS, DS, 0, n0, acc, As, Bs);
        storeR(g_R + 3*NIN*DS, n0, acc);
    } else if (p == 1) {
        tile32(g_R, g_G4, NIN, DS, DS, 0, n0, acc, As, Bs);
        storeR(g_R + 4*NIN*DS, n0, acc);
    } else {
        tile32(g_R + 1*NIN*DS, g_G4, NIN, DS, DS, 0, n0, acc, As, Bs);
        storeR(g_R + 5*NIN*DS, n0, acc);
    }
}

// L4: [R(168); bw(6)] @ CT -> g_Qf (half, [n][k]) + g_qb (float). 6 x 32 blocks.
__global__ void kt_gemmQ() {
    __shared__ float As[32][33], Bs[32][33];
    int tid = threadIdx.x;
    int tx = tid & 15, ty = tid >> 4;
    int m0 = (int)(blockIdx.x >> 5) * 32;
    int n0 = (int)(blockIdx.x & 31) * 32;
    float acc[2][2] = {};
    for (int k0 = 0; k0 < DS; k0 += 32) {
#pragma unroll
        for (int j = 0; j < 4; j++) {
            int e = j*256 + tid;
            int r = e >> 5, c = e & 31;
            int gm = m0 + r;
            float av = 0.f;
            if (gm < KTOT) av = g_R[(size_t)gm*DS + k0 + c];
            else if (gm < KTOT + NTAP) av = g_bw[(gm - KTOT)*DS + k0 + c];
            As[r][c] = av;
            Bs[r][c] = g_CT[(size_t)(k0 + r)*DM + n0 + c];
        }
        __syncthreads();
#pragma unroll
        for (int kk = 0; kk < 32; kk++) {
            float x0 = As[ty*2][kk],  x1 = As[ty*2+1][kk];
            float y0 = Bs[kk][tx*2],  y1 = Bs[kk][tx*2+1];
            acc[0][0] += x0*y0; acc[0][1] += x0*y1;
            acc[1][0] += x1*y0; acc[1][1] += x1*y1;
        }
        __syncthreads();
    }
    int n = n0 + tx*2;
#pragma unroll
    for (int rr = 0; rr < 2; rr++) {
        int m = m0 + ty*2 + rr;
        if (m < KTOT) {
            g_Qf[(size_t)n*KPAD + m]     = __float2half_rn(acc[rr][0]);
            g_Qf[(size_t)(n+1)*KPAD + m] = __float2half_rn(acc[rr][1]);
        } else if (m < KTOT + NTAP) {
            g_qb[(m - KTOT)*DM + n]   = acc[rr][0];
            g_qb[(m - KTOT)*DM + n+1] = acc[rr][1];
        }
    }
}

// ---------------- fp16 X expansion (smem gather, coalesced half2) ----------------
#define XT 64
__global__ void kt_halfX(const float* __restrict__ x) {
    __shared__ float xs[(XT+7)*NIN];
    int tid = threadIdx.x;
    int t0 = blockIdx.x * XT;
    int bbase = t0 & ~(NL-1);
    for (int e = tid; e < (XT+7)*NIN; e += 256) {
        int row = e / NIN, col = e - row*NIN;
        int gt = t0 - 7 + row;
        xs[e] = (gt >= bbase) ? x[(size_t)gt*NIN + col] : 0.f;
    }
    __syncthreads();
    for (int p = tid; p < XT*(KPAD/2); p += 256) {
        int tr = p / (KPAD/2), kp = (p - tr*(KPAD/2))*2;
        float v0 = 0.f, v1 = 0.f;
        if (kp < KTOT) {
            int b0 = kp / NIN, i0 = kp - b0*NIN;
            v0 = xs[(tr + 7 - b0)*NIN + i0];
        }
        if (kp + 1 < KTOT) {
            int b1 = (kp+1) / NIN, i1 = kp+1 - b1*NIN;
            v1 = xs[(tr + 7 - b1)*NIN + i1];
        }
        *(__half2*)&g_Xf[(size_t)(t0+tr)*KPAD + kp] = __floats2half2_rn(v0, v1);
    }
}

// ---------------- activation helpers ----------------
__device__ __forceinline__ float gelu_fast(float y) {
    float z = y * 0.70710678118654752f;
    float z2 = z*z;
    if (z2 < 0.25f) {
        float p = fmaf(z2, 1.0f/216.0f, -1.0f/42.0f);
        p = fmaf(z2, p, 0.1f);
        p = fmaf(z2, p, -1.0f/3.0f);
        p = fmaf(z2, p, 1.0f);
        float e = 1.12837916709551257f * z * p;
        return 0.5f * y * (1.0f + e);
    }
    return 0.5f * y * (1.0f + erff(z));
}
__device__ __forceinline__ float fixv(float v) {
    if (isnan(v)) return 0.f;
    if (isinf(v)) return v > 0.f ? 1000000.0f : -1000000.0f;
    return v;
}

// ======== fused fp16 GEMM + GELU + LayerNorm + store + pool ========
// CTA: 32 tokens x full 1024 cols. 512 threads = 16 warps (2 m-warps x 8 n-warps).
// Warp tile 16 x 128. 6 k-chunks of 32, double-buffered cp.async.
#define TTOK 32
#define ROWB 80
#define ASTG (TTOK*ROWB)        // 2560
#define BSTG (1024*ROWB)        // 81920
#define OFF_A 0
#define OFF_B (2*ASTG)          // 5120
#define SMEM_MMA (2*ASTG + 2*BSTG)   // 168960
#define YROW 1032
__global__ __launch_bounds__(512, 1) void kt_mma(const float* __restrict__ gamma,
                                                 const float* __restrict__ beta,
                                                 float* __restrict__ out) {
    extern __shared__ __align__(16) char smem[];
    const int tid = threadIdx.x, lane = tid & 31, warp = tid >> 5;
    const int wm = warp >> 3, wn = warp & 7;
    const int t0 = (int)blockIdx.x * TTOK;
    const int l0 = t0 & (NL-1);
    const uint32_t base = smem_u32(smem);

    auto issue = [&](int c, int buf) {
        int kb = c * 32;
#pragma unroll
        for (int i = 0; i < 8; i++) {
            int e = i*512 + tid;
            int row = e >> 2, g = e & 3;
            cp16(base + OFF_B + buf*BSTG + row*ROWB + g*16,
                 g_Qf + (size_t)row*KPAD + kb + g*8);
        }
        if (tid < 128) {
            int row = tid >> 2, g = tid & 3;
            cp16(base + OFF_A + buf*ASTG + row*ROWB + g*16,
                 g_Xf + (size_t)(t0 + row)*KPAD + kb + g*8);
        }
        cp_commit();
    };

    float acc[16][4];
#pragma unroll
    for (int nt = 0; nt < 16; nt++)
#pragma unroll
        for (int j = 0; j < 4; j++) acc[nt][j] = 0.f;

    issue(0, 0);
    for (int c = 0; c < NCHUNK; c++) {
        int buf = c & 1;
        if (c + 1 < NCHUNK) { issue(c + 1, (c + 1) & 1); cp_wait1(); }
        else cp_wait0();
        __syncthreads();

#pragma unroll
        for (int k16 = 0; k16 < 32; k16 += 16) {
            uint32_t afr[4];
            {
                int row = wm*16 + (lane & 15);
                int kk = k16 + ((lane >> 4) << 3);
                ldm_x4(afr, base + OFF_A + buf*ASTG + row*ROWB + kk*2);
            }
            int nbase = wn*128 + (lane & 7) + ((lane >> 4) << 3);
            int bkk = k16 + (((lane >> 3) & 1) << 3);
#pragma unroll
            for (int bt = 0; bt < 8; bt++) {
                uint32_t bfr[4];
                ldm_x4(bfr, base + OFF_B + buf*BSTG + (nbase + bt*16)*ROWB + bkk*2);
                mma16816(acc[2*bt],   afr, bfr[0], bfr[1]);
                mma16816(acc[2*bt+1], afr, bfr[2], bfr[3]);
            }
        }
        __syncthreads();
    }

    // ---- fused epilogue ----
    float* sm   = (float*)smem;
    float* redS = sm;            // [32][8]
    float* redQ = sm + 256;      // [32][8]
    float* muS  = sm + 512;      // [32]
    float* rsS  = sm + 544;      // [32]
    float* Ys   = sm + 576;      // [32][YROW]

    const int qr = lane >> 2, qc = (lane & 3) * 2;
    const int tokA = wm*16 + qr, tokB = tokA + 8;
    int lA = l0 + tokA; int sA = lA < NTAP-1 ? lA : NTAP-1;
    int lB = l0 + tokB; int sB = lB < NTAP-1 ? lB : NTAP-1;
    const float* qbA = g_qb + sA*DM;
    const float* qbB = g_qb + sB*DM;

    float s1A = 0.f, s2A = 0.f, s1B = 0.f, s2B = 0.f;
#pragma unroll
    for (int nt = 0; nt < 16; nt++) {
        int col = wn*128 + nt*8 + qc;
        float2 qa = *(const float2*)&qbA[col];
        float2 qb2 = *(const float2*)&qbB[col];
        float v0 = gelu_fast(acc[nt][0] + qa.x);
        float v1 = gelu_fast(acc[nt][1] + qa.y);
        float v2 = gelu_fast(acc[nt][2] + qb2.x);
        float v3 = gelu_fast(acc[nt][3] + qb2.y);
        acc[nt][0] = v0; acc[nt][1] = v1; acc[nt][2] = v2; acc[nt][3] = v3;
        s1A += v0 + v1; s2A += v0*v0 + v1*v1;
        s1B += v2 + v3; s2B += v2*v2 + v3*v3;
    }
#pragma unroll
    for (int off = 1; off <= 2; off <<= 1) {
        s1A += __shfl_xor_sync(0xffffffffu, s1A, off);
        s2A += __shfl_xor_sync(0xffffffffu, s2A, off);
        s1B += __shfl_xor_sync(0xffffffffu, s1B, off);
        s2B += __shfl_xor_sync(0xffffffffu, s2B, off);
    }
    if ((lane & 3) == 0) {
        redS[tokA*8 + wn] = s1A; redQ[tokA*8 + wn] = s2A;
        redS[tokB*8 + wn] = s1B; redQ[tokB*8 + wn] = s2B;
    }
    __syncthreads();
    if (tid < 32) {
        float a = 0.f, b2 = 0.f;
#pragma unroll
        for (int w = 0; w < 8; w++) { a += redS[tid*8 + w]; b2 += redQ[tid*8 + w]; }
        float mu = a * (1.0f/DM);
        muS[tid] = mu;
        rsS[tid] = rsqrtf(b2 * (1.0f/DM) - mu*mu + 1e-5f);
    }
    __syncthreads();
    const float muA = muS[tokA], rsA = rsS[tokA];
    const float muB = muS[tokB], rsB = rsS[tokB];
#pragma unroll
    for (int nt = 0; nt < 16; nt++) {
        int col = wn*128 + nt*8 + qc;
        float2 gg = *(const float2*)&gamma[col];
        float2 bb = *(const float2*)&beta[col];
        float2 oA, oB;
        oA.x = fixv((acc[nt][0] - muA)*rsA*gg.x + bb.x);
        oA.y = fixv((acc[nt][1] - muA)*rsA*gg.y + bb.y);
        oB.x = fixv((acc[nt][2] - muB)*rsB*gg.x + bb.x);
        oB.y = fixv((acc[nt][3] - muB)*rsB*gg.y + bb.y);
        *(float2*)&Ys[tokA*YROW + col] = oA;
        *(float2*)&Ys[tokB*YROW + col] = oB;
    }
    __syncthreads();

    // coalesced out write + pool accumulation
    const int c4 = tid & 255;
    float p0 = 0.f, p1 = 0.f, p2 = 0.f, p3 = 0.f;
#pragma unroll
    for (int i = 0; i < 16; i++) {
        int row = (tid >> 8) + i*2;
        float4 v = *(const float4*)&Ys[row*YROW + c4*4];
        *(float4*)&out[(size_t)LOGITS_OFF + (size_t)(t0 + row)*DM + c4*4] = v;
        p0 += v.x; p1 += v.y; p2 += v.z; p3 += v.w;
    }
    const float inv = 1.0f / (float)NL;
    float* pp = &g_pooled[(t0 >> 10)*DM + c4*4];
    atomicAdd(pp+0, p0*inv);
    atomicAdd(pp+1, p1*inv);
    atomicAdd(pp+2, p2*inv);
    atomicAdd(pp+3, p3*inv);
}

// ---------------- logits ----------------
__global__ void kt_logits(const float* __restrict__ W_fc, const float* __restrict__ b_fc,
                          float* __restrict__ out) {
    int b = blockIdx.x;
    int lane = threadIdx.x;
    for (int c = 0; c < NCL; c++) {
        float s = 0.f;
        for (int d = lane; d < DM; d += 32)
            s += g_pooled[b*DM + d] * W_fc[c*DM + d];
#pragma unroll
        for (int off = 16; off > 0; off >>= 1)
            s += __shfl_down_sync(0xffffffffu, s, off);
        if (lane == 0) out[b*NCL + c] = s + b_fc[c];
    }
}

// ---------------- launch ----------------
extern "C" void kernel_launch(void* const* d_in, const int* in_sizes, int n_in,
                              void* d_out, int out_size) {
    const float* x     = (const float*)d_in[0];
    const float* W_in  = (const float*)d_in[1];
    const float* b_in  = (const float*)d_in[2];
    const float* A     = (const float*)d_in[3];
    const float* Bm    = (const float*)d_in[4];
    const float* C     = (const float*)d_in[5];
    const float* gamma = (const float*)d_in[6];
    const float* beta  = (const float*)d_in[7];
    const float* W_fc  = (const float*)d_in[8];
    const float* b_fc  = (const float*)d_in[9];
    float* out = (float*)d_out;

    static int inited = 0;
    if (!inited) {
        cudaFuncSetAttribute(kt_mma, cudaFuncAttributeMaxDynamicSharedMemorySize, SMEM_MMA);
        inited = 1;
    }

    kt_prep<<<1536 + DM*KPAD/512, 256>>>(A, C);   // G, CT, zero pooled + Qf
    kt_bvbias<<<1, 256>>>(Bm, b_in);              // bw chain (needs G)
    kt_precomp1<<<72, 256>>>(Bm, W_in);           // G2, R0
    kt_precomp2<<<80, 256>>>();                   // G4, R1, R2
    kt_precomp3<<<24, 256>>>();                   // R3, R4, R5
    kt_gemmQ<<<192, 256>>>();                     // Qf (half, [n][k]) + qb
    kt_halfX<<<NT/XT, 256>>>(x);                  // Xf
    kt_mma<<<NT/TTOK, 512, SMEM_MMA>>>(gamma, beta, out);
    kt_logits<<<NB, 32>>>(W_fc, b_fc, out);
}

// round 17
// speedup vs baseline: 1.1568x; 1.1231x over previous
#include <cuda_runtime.h>
#include <cuda_fp16.h>
#include <math.h>
#include <stdint.h>

// ---------------- problem constants ----------------
#define NB   64
#define NL   1024
#define NT   65536        // NB*NL tokens
#define DM   1024
#define DS   256
#define NIN  28
#define NCL  10
#define NTAP 6
#define KTOT (NTAP*NIN)   // 168
#define KPAD 192          // 6 chunks of 32
#define NCHUNK 6
#define LOGITS_OFF 640    // NB*NCL floats, activations follow
#define MROWS (KTOT+NTAP) // 174 rows of [R; bias]

// ---------------- device scratch ----------------
__device__ float g_G [DS*DS];
__device__ float g_G2[DS*DS];
__device__ float g_G4[DS*DS];
__device__ float g_R [MROWS*DS];         // taps 0..5 (168 rows) + bias rows (6)
__device__ float g_CT[DS*DM];
__device__ float g_qb[NTAP*DM];
__device__ float g_pooled[NB*DM];
__device__ __half g_Xf[(size_t)NT*KPAD];   // 24MB
__device__ __half g_Qf[(size_t)DM*KPAD];   // [n][k]

// ---------------- asm helpers ----------------
__device__ __forceinline__ uint32_t smem_u32(const void* p) {
    uint32_t a;
    asm("{ .reg .u64 t; cvta.to.shared.u64 t, %1; cvt.u32.u64 %0, t; }" : "=r"(a) : "l"(p));
    return a;
}
__device__ __forceinline__ void cp16(uint32_t dst, const void* src) {
    asm volatile("cp.async.cg.shared.global [%0], [%1], 16;" :: "r"(dst), "l"(src));
}
__device__ __forceinline__ void cp_commit() {
    asm volatile("cp.async.commit_group;" ::: "memory");
}
__device__ __forceinline__ void cp_wait1() {
    asm volatile("cp.async.wait_group 1;" ::: "memory");
}
__device__ __forceinline__ void cp_wait0() {
    asm volatile("cp.async.wait_group 0;" ::: "memory");
}
__device__ __forceinline__ void ldm_x4(uint32_t* r, uint32_t addr) {
    asm volatile("ldmatrix.sync.aligned.m8n8.x4.shared.b16 {%0,%1,%2,%3}, [%4];"
                 : "=r"(r[0]), "=r"(r[1]), "=r"(r[2]), "=r"(r[3]) : "r"(addr));
}
__device__ __forceinline__ void mma16816(float* c, const uint32_t* a, uint32_t b0, uint32_t b1) {
    asm volatile("mma.sync.aligned.m16n8k16.row.col.f32.f16.f16.f32 "
                 "{%0,%1,%2,%3}, {%4,%5,%6,%7}, {%8,%9}, {%0,%1,%2,%3};"
                 : "+f"(c[0]), "+f"(c[1]), "+f"(c[2]), "+f"(c[3])
                 : "r"(a[0]), "r"(a[1]), "r"(a[2]), "r"(a[3]), "r"(b0), "r"(b1));
}

// ---------------- 64x64 fp32 tile (device body), 256 threads, 4x4/thread ------
__device__ __forceinline__ void tile64(const float* __restrict__ Aa,
                                       const float* __restrict__ Bb,
                                       int M, int N, int K, int m0, int n0,
                                       float acc[4][4],
                                       float (*As)[33], float (*Bs)[65]) {
    int tx = threadIdx.x & 15, ty = threadIdx.x >> 4;
#pragma unroll
    for (int r = 0; r < 4; r++)
#pragma unroll
        for (int c = 0; c < 4; c++) acc[r][c] = 0.f;
    for (int k0 = 0; k0 < K; k0 += 32) {
#pragma unroll
        for (int j = 0; j < 8; j++) {
            int e = j*256 + threadIdx.x;
            int r = e >> 5, c = e & 31;       // A: 64 x 32
            As[r][c] = (m0+r < M && k0+c < K) ? Aa[(size_t)(m0+r)*K + k0+c] : 0.f;
            int r2 = e >> 6, c2 = e & 63;     // B: 32 x 64
            Bs[r2][c2] = (k0+r2 < K && n0+c2 < N) ? Bb[(size_t)(k0+r2)*N + n0+c2] : 0.f;
        }
        __syncthreads();
#pragma unroll
        for (int kk = 0; kk < 32; kk++) {
            float a[4], b[4];
#pragma unroll
            for (int r = 0; r < 4; r++) a[r] = As[ty*4+r][kk];
#pragma unroll
            for (int c = 0; c < 4; c++) b[c] = Bs[kk][tx*4+c];
#pragma unroll
            for (int r = 0; r < 4; r++)
#pragma unroll
                for (int c = 0; c < 4; c++) acc[r][c] = fmaf(a[r], b[c], acc[r][c]);
        }
        __syncthreads();
    }
}
__device__ __forceinline__ void store64(float* Oo, int N, int m0, int n0, int M,
                                        float acc[4][4]) {
    int tx = threadIdx.x & 15, ty = threadIdx.x >> 4;
#pragma unroll
    for (int r = 0; r < 4; r++) {
        int m = m0 + ty*4 + r;
        if (m >= M) continue;
#pragma unroll
        for (int c = 0; c < 4; c++) {
            int n = n0 + tx*4 + c;
            if (n < N) Oo[(size_t)m*N + n] = acc[r][c];
        }
    }
}

// ---------------- kt_prep: transposes + zeros + halfX (all independent) ------
#define XT 64
__global__ void kt_prep(const float* __restrict__ A, const float* __restrict__ C,
                        const float* __restrict__ x) {
    __shared__ float xs[(XT+7)*NIN];
    int b = blockIdx.x;
    int tid = threadIdx.x;
    if (b < 256) {                     // G = A^T
        int idx = b*256 + tid;
        int r = idx >> 8, c = idx & 255;
        g_G[c*DS + r] = A[idx];
    } else if (b < 1280) {             // CT = C^T
        int idx = (b - 256)*256 + tid;
        int r = idx >> 8, c = idx & 255;
        g_CT[c*DM + r] = C[idx];
    } else if (b < 1536) {             // zero pooled
        int i = (b - 1280)*256 + tid;
        g_pooled[i] = 0.0f;
    } else if (b < 1920) {             // zero Qf (incl. pad rows)
        int i = (b - 1536)*256 + tid;
        ((uint32_t*)g_Qf)[i] = 0u;
    } else {                           // halfX: token tile
        int t0 = (b - 1920) * XT;
        int bbase = t0 & ~(NL-1);
        for (int e = tid; e < (XT+7)*NIN; e += 256) {
            int row = e / NIN, col = e - row*NIN;
            int gt = t0 - 7 + row;
            xs[e] = (gt >= bbase) ? x[(size_t)gt*NIN + col] : 0.f;
        }
        __syncthreads();
        for (int p = tid; p < XT*(KPAD/2); p += 256) {
            int tr = p / (KPAD/2), kp = (p - tr*(KPAD/2))*2;
            float v0 = 0.f, v1 = 0.f;
            if (kp < KTOT) {
                int b0 = kp / NIN, i0 = kp - b0*NIN;
                v0 = xs[(tr + 7 - b0)*NIN + i0];
            }
            if (kp + 1 < KTOT) {
                int b1 = (kp+1) / NIN, i1 = kp+1 - b1*NIN;
                v1 = xs[(tr + 7 - b1)*NIN + i1];
            }
            *(__half2*)&g_Xf[(size_t)(t0+tr)*KPAD + kp] = __floats2half2_rn(v0, v1);
        }
    }
}

// ---------------- p1: G2 (16) + R0 transposed (4) + bias chain (1) ------------
__global__ void kt_p1(const float* __restrict__ Bm, const float* __restrict__ W_in,
                      const float* __restrict__ b_in) {
    __shared__ float As[64][33];
    __shared__ float Bs[32][65];
    __shared__ float cur[DS], bvs[DS];
    int b = blockIdx.x;
    float acc[4][4];
    if (b < 16) {
        int m0 = (b >> 2)*64, n0 = (b & 3)*64;
        tile64(g_G, g_G, DS, DS, DS, m0, n0, acc, As, Bs);
        store64(g_G2, DS, m0, n0, DS, acc);
    } else if (b < 20) {
        int m0 = (b - 16)*64;
        tile64(Bm, W_in, DS, NIN, DM, m0, 0, acc, As, Bs);
        // store transposed: R0[n][m]
        int tx = threadIdx.x & 15, ty = threadIdx.x >> 4;
#pragma unroll
        for (int r = 0; r < 4; r++) {
            int m = m0 + ty*4 + r;
#pragma unroll
            for (int c = 0; c < 4; c++) {
                int n = tx*4 + c;
                if (n < NIN) g_R[(size_t)n*DS + m] = acc[r][c];
            }
        }
    } else {
        // bias: bv = Bm@b_in (warp gemv), then prefix chain into g_R tail rows
        int tid = threadIdx.x, lane = tid & 31, warp = tid >> 5;
        for (int r8 = 0; r8 < 32; r8++) {
            int row = warp*32 + r8;
            float s = 0.f;
            for (int k = lane; k < DM; k += 32) s += Bm[(size_t)row*DM + k] * b_in[k];
#pragma unroll
            for (int off = 16; off > 0; off >>= 1) s += __shfl_xor_sync(0xffffffffu, s, off);
            if (lane == 0) bvs[row] = s;
        }
        __syncthreads();
        int c = tid;
        float v = bvs[c];
        cur[c] = v;
        float accum = v;
        g_R[(size_t)(KTOT + 0)*DS + c] = v;
        for (int s = 1; s < NTAP; s++) {
            __syncthreads();
            float nxt = 0.f;
#pragma unroll 8
            for (int k = 0; k < DS; k++) nxt += cur[k] * g_G[k*DS + c];
            __syncthreads();
            cur[c] = nxt;
            accum += nxt;
            g_R[(size_t)(KTOT + s)*DS + c] = accum;
        }
    }
}

// ---------------- p2: G4 (16) + R1 = R0@G (4) + R2 = R0@G2 (4) ----------------
__global__ void kt_p2() {
    __shared__ float As[64][33];
    __shared__ float Bs[32][65];
    int b = blockIdx.x;
    float acc[4][4];
    if (b < 16) {
        int m0 = (b >> 2)*64, n0 = (b & 3)*64;
        tile64(g_G2, g_G2, DS, DS, DS, m0, n0, acc, As, Bs);
        store64(g_G4, DS, m0, n0, DS, acc);
    } else if (b < 20) {
        int n0 = (b - 16)*64;
        tile64(g_R, g_G, NIN, DS, DS, 0, n0, acc, As, Bs);
        store64(g_R + 1*NIN*DS, DS, 0, n0, NIN, acc);
    } else {
        int n0 = (b - 20)*64;
        tile64(g_R, g_G2, NIN, DS, DS, 0, n0, acc, As, Bs);
        store64(g_R + 2*NIN*DS, DS, 0, n0, NIN, acc);
    }
}

// ---------------- p3: R3 = R1@G2 (4) + R4 = R0@G4 (4) + R5 = R1@G4 (4) --------
__global__ void kt_p3() {
    __shared__ float As[64][33];
    __shared__ float Bs[32][65];
    int b = blockIdx.x;
    float acc[4][4];
    int p = b >> 2, n0 = (b & 3)*64;
    if (p == 0) {
        tile64(g_R + 1*NIN*DS, g_G2, NIN, DS, DS, 0, n0, acc, As, Bs);
        store64(g_R + 3*NIN*DS, DS, 0, n0, NIN, acc);
    } else if (p == 1) {
        tile64(g_R, g_G4, NIN, DS, DS, 0, n0, acc, As, Bs);
        store64(g_R + 4*NIN*DS, DS, 0, n0, NIN, acc);
    } else {
        tile64(g_R + 1*NIN*DS, g_G4, NIN, DS, DS, 0, n0, acc, As, Bs);
        store64(g_R + 5*NIN*DS, DS, 0, n0, NIN, acc);
    }
}

// ---------------- gemmQ: [R;bias](174x256) @ CT -> Qf(half,[n][k]) + qb -------
__global__ void kt_gemmQ() {
    __shared__ float As[64][33];
    __shared__ float Bs[32][65];
    float acc[4][4];
    int m0 = (int)(blockIdx.x >> 4) * 64;   // 3 m-tiles
    int n0 = (int)(blockIdx.x & 15) * 64;   // 16 n-tiles
    tile64(g_R, g_CT, MROWS, DM, DS, m0, n0, acc, As, Bs);
    int tx = threadIdx.x & 15, ty = threadIdx.x >> 4;
#pragma unroll
    for (int r = 0; r < 4; r++) {
        int m = m0 + ty*4 + r;
        if (m >= MROWS) continue;
#pragma unroll
        for (int c = 0; c < 4; c++) {
            int n = n0 + tx*4 + c;
            if (m < KTOT) g_Qf[(size_t)n*KPAD + m] = __float2half_rn(acc[r][c]);
            else          g_qb[(m - KTOT)*DM + n]  = acc[r][c];
        }
    }
}

// ---------------- activation helpers ----------------
__device__ __forceinline__ float gelu_fast(float y) {
    float z = y * 0.70710678118654752f;
    float z2 = z*z;
    if (z2 < 0.25f) {
        float p = fmaf(z2, 1.0f/216.0f, -1.0f/42.0f);
        p = fmaf(z2, p, 0.1f);
        p = fmaf(z2, p, -1.0f/3.0f);
        p = fmaf(z2, p, 1.0f);
        float e = 1.12837916709551257f * z * p;
        return 0.5f * y * (1.0f + e);
    }
    return 0.5f * y * (1.0f + erff(z));
}
__device__ __forceinline__ float fixv(float v) {
    if (isnan(v)) return 0.f;
    if (isinf(v)) return v > 0.f ? 1000000.0f : -1000000.0f;
    return v;
}

// ======== fused fp16 GEMM + GELU + LayerNorm + store + pool ========
// CTA: 32 tokens x full 1024 cols. 512 threads = 16 warps (2 m-warps x 8 n-warps).
#define TTOK 32
#define ROWB 80
#define ASTG (TTOK*ROWB)        // 2560
#define BSTG (1024*ROWB)        // 81920
#define OFF_A 0
#define OFF_B (2*ASTG)          // 5120
#define SMEM_MMA (2*ASTG + 2*BSTG)   // 168960
#define YROW 1032
__global__ __launch_bounds__(512, 1) void kt_mma(const float* __restrict__ gamma,
                                                 const float* __restrict__ beta,
                                                 float* __restrict__ out) {
    extern __shared__ __align__(16) char smem[];
    const int tid = threadIdx.x, lane = tid & 31, warp = tid >> 5;
    const int wm = warp >> 3, wn = warp & 7;
    const int t0 = (int)blockIdx.x * TTOK;
    const int l0 = t0 & (NL-1);
    const uint32_t base = smem_u32(smem);

    auto issue = [&](int c, int buf) {
        int kb = c * 32;
#pragma unroll
        for (int i = 0; i < 8; i++) {
            int e = i*512 + tid;
            int row = e >> 2, g = e & 3;
            cp16(base + OFF_B + buf*BSTG + row*ROWB + g*16,
                 g_Qf + (size_t)row*KPAD + kb + g*8);
        }
        if (tid < 128) {
            int row = tid >> 2, g = tid & 3;
            cp16(base + OFF_A + buf*ASTG + row*ROWB + g*16,
                 g_Xf + (size_t)(t0 + row)*KPAD + kb + g*8);
        }
        cp_commit();
    };

    float acc[16][4];
#pragma unroll
    for (int nt = 0; nt < 16; nt++)
#pragma unroll
        for (int j = 0; j < 4; j++) acc[nt][j] = 0.f;

    issue(0, 0);
    for (int c = 0; c < NCHUNK; c++) {
        int buf = c & 1;
        if (c + 1 < NCHUNK) { issue(c + 1, (c + 1) & 1); cp_wait1(); }
        else cp_wait0();
        __syncthreads();

#pragma unroll
        for (int k16 = 0; k16 < 32; k16 += 16) {
            uint32_t afr[4];
            {
                int row = wm*16 + (lane & 15);
                int kk = k16 + ((lane >> 4) << 3);
                ldm_x4(afr, base + OFF_A + buf*ASTG + row*ROWB + kk*2);
            }
            int nbase = wn*128 + (lane & 7) + ((lane >> 4) << 3);
            int bkk = k16 + (((lane >> 3) & 1) << 3);
#pragma unroll
            for (int bt = 0; bt < 8; bt++) {
                uint32_t bfr[4];
                ldm_x4(bfr, base + OFF_B + buf*BSTG + (nbase + bt*16)*ROWB + bkk*2);
                mma16816(acc[2*bt],   afr, bfr[0], bfr[1]);
                mma16816(acc[2*bt+1], afr, bfr[2], bfr[3]);
            }
        }
        __syncthreads();
    }

    // ---- fused epilogue ----
    float* sm   = (float*)smem;
    float* redS = sm;            // [32][8]
    float* redQ = sm + 256;      // [32][8]
    float* muS  = sm + 512;      // [32]
    float* rsS  = sm + 544;      // [32]
    float* Ys   = sm + 576;      // [32][YROW]

    const int qr = lane >> 2, qc = (lane & 3) * 2;
    const int tokA = wm*16 + qr, tokB = tokA + 8;
    int lA = l0 + tokA; int sA = lA < NTAP-1 ? lA : NTAP-1;
    int lB = l0 + tokB; int sB = lB < NTAP-1 ? lB : NTAP-1;
    const float* qbA = g_qb + sA*DM;
    const float* qbB = g_qb + sB*DM;

    float s1A = 0.f, s2A = 0.f, s1B = 0.f, s2B = 0.f;
#pragma unroll
    for (int nt = 0; nt < 16; nt++) {
        int col = wn*128 + nt*8 + qc;
        float2 qa = *(const float2*)&qbA[col];
        float2 qb2 = *(const float2*)&qbB[col];
        float v0 = gelu_fast(acc[nt][0] + qa.x);
        float v1 = gelu_fast(acc[nt][1] + qa.y);
        float v2 = gelu_fast(acc[nt][2] + qb2.x);
        float v3 = gelu_fast(acc[nt][3] + qb2.y);
        acc[nt][0] = v0; acc[nt][1] = v1; acc[nt][2] = v2; acc[nt][3] = v3;
        s1A += v0 + v1; s2A += v0*v0 + v1*v1;
        s1B += v2 + v3; s2B += v2*v2 + v3*v3;
    }
#pragma unroll
    for (int off = 1; off <= 2; off <<= 1) {
        s1A += __shfl_xor_sync(0xffffffffu, s1A, off);
        s2A += __shfl_xor_sync(0xffffffffu, s2A, off);
        s1B += __shfl_xor_sync(0xffffffffu, s1B, off);
        s2B += __shfl_xor_sync(0xffffffffu, s2B, off);
    }
    if ((lane & 3) == 0) {
        redS[tokA*8 + wn] = s1A; redQ[tokA*8 + wn] = s2A;
        redS[tokB*8 + wn] = s1B; redQ[tokB*8 + wn] = s2B;
    }
    __syncthreads();
    if (tid < 32) {
        float a = 0.f, b2 = 0.f;
#pragma unroll
        for (int w = 0; w < 8; w++) { a += redS[tid*8 + w]; b2 += redQ[tid*8 + w]; }
        float mu = a * (1.0f/DM);
        muS[tid] = mu;
        rsS[tid] = rsqrtf(b2 * (1.0f/DM) - mu*mu + 1e-5f);
    }
    __syncthreads();
    const float muA = muS[tokA], rsA = rsS[tokA];
    const float muB = muS[tokB], rsB = rsS[tokB];
#pragma unroll
    for (int nt = 0; nt < 16; nt++) {
        int col = wn*128 + nt*8 + qc;
        float2 gg = *(const float2*)&gamma[col];
        float2 bb = *(const float2*)&beta[col];
        float2 oA, oB;
        oA.x = fixv((acc[nt][0] - muA)*rsA*gg.x + bb.x);
        oA.y = fixv((acc[nt][1] - muA)*rsA*gg.y + bb.y);
        oB.x = fixv((acc[nt][2] - muB)*rsB*gg.x + bb.x);
        oB.y = fixv((acc[nt][3] - muB)*rsB*gg.y + bb.y);
        *(float2*)&Ys[tokA*YROW + col] = oA;
        *(float2*)&Ys[tokB*YROW + col] = oB;
    }
    __syncthreads();

    const int c4 = tid & 255;
    float p0 = 0.f, p1 = 0.f, p2 = 0.f, p3 = 0.f;
#pragma unroll
    for (int i = 0; i < 16; i++) {
        int row = (tid >> 8) + i*2;
        float4 v = *(const float4*)&Ys[row*YROW + c4*4];
        *(float4*)&out[(size_t)LOGITS_OFF + (size_t)(t0 + row)*DM + c4*4] = v;
        p0 += v.x; p1 += v.y; p2 += v.z; p3 += v.w;
    }
    const float inv = 1.0f / (float)NL;
    float* pp = &g_pooled[(t0 >> 10)*DM + c4*4];
    atomicAdd(pp+0, p0*inv);
    atomicAdd(pp+1, p1*inv);
    atomicAdd(pp+2, p2*inv);
    atomicAdd(pp+3, p3*inv);
}

// ---------------- logits ----------------
__global__ void kt_logits(const float* __restrict__ W_fc, const float* __restrict__ b_fc,
                          float* __restrict__ out) {
    int b = blockIdx.x;
    int lane = threadIdx.x;
    for (int c = 0; c < NCL; c++) {
        float s = 0.f;
        for (int d = lane; d < DM; d += 32)
            s += g_pooled[b*DM + d] * W_fc[c*DM + d];
#pragma unroll
        for (int off = 16; off > 0; off >>= 1)
            s += __shfl_down_sync(0xffffffffu, s, off);
        if (lane == 0) out[b*NCL + c] = s + b_fc[c];
    }
}

// ---------------- launch ----------------
extern "C" void kernel_launch(void* const* d_in, const int* in_sizes, int n_in,
                              void* d_out, int out_size) {
    const float* x     = (const float*)d_in[0];
    const float* W_in  = (const float*)d_in[1];
    const float* b_in  = (const float*)d_in[2];
    const float* A     = (const float*)d_in[3];
    const float* Bm    = (const float*)d_in[4];
    const float* C     = (const float*)d_in[5];
    const float* gamma = (const float*)d_in[6];
    const float* beta  = (const float*)d_in[7];
    const float* W_fc  = (const float*)d_in[8];
    const float* b_fc  = (const float*)d_in[9];
    float* out = (float*)d_out;

    static int inited = 0;
    if (!inited) {
        cudaFuncSetAttribute(kt_mma, cudaFuncAttributeMaxDynamicSharedMemorySize, SMEM_MMA);
        inited = 1;
    }

    // prep: G^T, C^T, zero pooled+Qf, halfX  (1920 + 1024 blocks)
    kt_prep<<<1920 + NT/XT, 256>>>(A, C, x);
    kt_p1<<<21, 256>>>(Bm, W_in, b_in);           // G2, R0, bias rows
    kt_p2<<<24, 256>>>();                         // G4, R1, R2
    kt_p3<<<12, 256>>>();                         // R3, R4, R5
    kt_gemmQ<<<48, 256>>>();                      // Qf (half, [n][k]) + qb
    kt_mma<<<NT/TTOK, 512, SMEM_MMA>>>(gamma, beta, out);
    kt_logits<<<NB, 32>>>(W_fc, b_fc, out);
}